// round 2
// baseline (speedup 1.0000x reference)
#include <cuda_runtime.h>
#include <math.h>

#define BB   4
#define SS   2048
#define DIMC 2048
#define NH   16
#define NKV  4
#define HD   128
#define QKVC 3072
#define EPSF 1.1920928955078125e-07f
#define NEGF -1e30f

// Scratch (device globals: allocation-free per harness rules)
__device__ float g_qkv[(size_t)BB * SS * QKVC];   // 96 MB
__device__ float g_attn[(size_t)BB * SS * DIMC];  // 64 MB
__device__ unsigned char g_mask[BB * SS];         // canonical 0/1 mask

// ---------------------------------------------------------------------------
// Mask canonicalization: detect on-device dtype of vis_mask and write 0/1
// bytes into g_mask. Deterministic, single block.
//   float32: some byte at index 4i+3 == 0x3F (bit pattern of 1.0f)
//   bool/u8: some byte at index i%4 != 0 is nonzero (values are 0/1 bytes)
//   int32:   otherwise (little-endian 0/1 ints: only bytes 4i can be 1)
// ---------------------------------------------------------------------------
__global__ __launch_bounds__(256) void mask_prep(const unsigned char* __restrict__ raw)
{
    __shared__ int kind;  // 0=int32, 1=bool/u8, 2=float32
    if (threadIdx.x == 0) kind = 0;
    __syncthreads();
    const int NTOK = BB * SS;
    for (int i = threadIdx.x; i < NTOK; i += 256) {   // scan first 8192 bytes
        unsigned char v = raw[i];
        if ((i & 3) == 3 && v == 0x3F) kind = 2;      // benign race
        else if ((i & 3) != 0 && v != 0) kind = 1;
    }
    __syncthreads();
    int k = kind;
    for (int i = threadIdx.x; i < NTOK; i += 256) {
        unsigned char m;
        if (k == 2)      m = (((const float*)raw)[i] != 0.0f);
        else if (k == 1) m = (raw[i] != 0);
        else             m = (((const int*)raw)[i] != 0);
        g_mask[i] = m;
    }
}

// ---------------------------------------------------------------------------
// GEMM: C[M,N] = A[M,K] * B[N,K]^T   (both operands K-contiguous, row-major)
// 128x128x16 tile, 256 threads, 8x8 per-thread microtile.
// ---------------------------------------------------------------------------
__global__ __launch_bounds__(256) void gemm_nt(const float* __restrict__ A,
                                               const float* __restrict__ Bm,
                                               float* __restrict__ C,
                                               int M, int N, int K)
{
    __shared__ float As[16][128];
    __shared__ float Bs[16][128];

    const int m0 = blockIdx.y * 128;
    const int n0 = blockIdx.x * 128;
    const int t  = threadIdx.x;
    const int lr = t >> 2;          // 0..63
    const int lk = (t & 3) << 2;    // 0,4,8,12
    const int ty = t >> 4;          // 0..15
    const int tx = t & 15;          // 0..15

    float acc[8][8];
#pragma unroll
    for (int i = 0; i < 8; i++)
#pragma unroll
        for (int j = 0; j < 8; j++) acc[i][j] = 0.f;

    for (int k0 = 0; k0 < K; k0 += 16) {
        __syncthreads();
        float4 a0 = *(const float4*)(A  + (size_t)(m0 + lr)      * K + k0 + lk);
        float4 a1 = *(const float4*)(A  + (size_t)(m0 + lr + 64) * K + k0 + lk);
        float4 b0 = *(const float4*)(Bm + (size_t)(n0 + lr)      * K + k0 + lk);
        float4 b1 = *(const float4*)(Bm + (size_t)(n0 + lr + 64) * K + k0 + lk);
        As[lk + 0][lr]      = a0.x; As[lk + 1][lr]      = a0.y;
        As[lk + 2][lr]      = a0.z; As[lk + 3][lr]      = a0.w;
        As[lk + 0][lr + 64] = a1.x; As[lk + 1][lr + 64] = a1.y;
        As[lk + 2][lr + 64] = a1.z; As[lk + 3][lr + 64] = a1.w;
        Bs[lk + 0][lr]      = b0.x; Bs[lk + 1][lr]      = b0.y;
        Bs[lk + 2][lr]      = b0.z; Bs[lk + 3][lr]      = b0.w;
        Bs[lk + 0][lr + 64] = b1.x; Bs[lk + 1][lr + 64] = b1.y;
        Bs[lk + 2][lr + 64] = b1.z; Bs[lk + 3][lr + 64] = b1.w;
        __syncthreads();

#pragma unroll
        for (int kk = 0; kk < 16; kk++) {
            float4 av0 = *(const float4*)&As[kk][ty * 4];
            float4 av1 = *(const float4*)&As[kk][64 + ty * 4];
            float4 bv0 = *(const float4*)&Bs[kk][tx * 4];
            float4 bv1 = *(const float4*)&Bs[kk][64 + tx * 4];
            float a[8] = {av0.x, av0.y, av0.z, av0.w, av1.x, av1.y, av1.z, av1.w};
            float b[8] = {bv0.x, bv0.y, bv0.z, bv0.w, bv1.x, bv1.y, bv1.z, bv1.w};
#pragma unroll
            for (int i = 0; i < 8; i++)
#pragma unroll
                for (int j = 0; j < 8; j++) acc[i][j] += a[i] * b[j];
        }
    }

#pragma unroll
    for (int i = 0; i < 8; i++) {
        int row = m0 + ((i < 4) ? (ty * 4 + i) : (64 + ty * 4 + i - 4));
        float4 o0 = make_float4(acc[i][0], acc[i][1], acc[i][2], acc[i][3]);
        float4 o1 = make_float4(acc[i][4], acc[i][5], acc[i][6], acc[i][7]);
        *(float4*)(C + (size_t)row * N + n0 + tx * 4)       = o0;
        *(float4*)(C + (size_t)row * N + n0 + 64 + tx * 4)  = o1;
    }
}

// ---------------------------------------------------------------------------
// Fused per-head RMSNorm + interleaved RoPE (in-place on qkv buffer).
// grid: (20 heads, S, B), block 128 (= HD).
// ---------------------------------------------------------------------------
__global__ __launch_bounds__(128) void norm_rope_kernel(float* __restrict__ qkv,
                                                        const float* __restrict__ qw,
                                                        const float* __restrict__ kw,
                                                        const float* __restrict__ fcos,
                                                        const float* __restrict__ fsin)
{
    const int head = blockIdx.x;   // 0..19 : 0..15 q heads, 16..19 k heads
    const int s    = blockIdx.y;
    const int b    = blockIdx.z;
    const int t    = threadIdx.x;

    const size_t rowbase = ((size_t)(b * SS + s)) * QKVC;
    const int off = (head < NH) ? head * HD : DIMC + (head - NH) * HD;
    const float* w = (head < NH) ? qw : kw;

    float x = qkv[rowbase + off + t];

    float ssum = x * x;
#pragma unroll
    for (int o = 16; o > 0; o >>= 1) ssum += __shfl_xor_sync(0xffffffffu, ssum, o);
    __shared__ float red[4];
    if ((t & 31) == 0) red[t >> 5] = ssum;
    __syncthreads();
    float tot = red[0] + red[1] + red[2] + red[3];
    float r = rsqrtf(tot * (1.f / HD) + EPSF);

    float xn = x * r * w[t];
    float partner = __shfl_xor_sync(0xffffffffu, xn, 1);
    float rot = (t & 1) ? partner : -partner;
    float c = fcos[s * HD + t];
    float sn = fsin[s * HD + t];
    qkv[rowbase + off + t] = xn * c + rot * sn;
}

// ---------------------------------------------------------------------------
// Flash-style GQA attention. Block = (64 queries, head h, batch b).
// 256 threads: ty=tid/16 owns 4 query rows, tx=tid%16 owns 4 score cols /
// 8 output cols. Q/K in smem d-major with XOR swizzle; V natural; P padded.
// ---------------------------------------------------------------------------
#define ATT_SMEM_FLOATS (8192 * 3 + 64 * 65 + 64)
#define ATT_SMEM_BYTES  (ATT_SMEM_FLOATS * 4)

__global__ __launch_bounds__(256) void attn_kernel(const float* __restrict__ qkv,
                                                   const unsigned char* __restrict__ vis,
                                                   float* __restrict__ outp)
{
    extern __shared__ float sm[];
    float* Qs = sm;                  // [128 d][64 m] swizzled
    float* Ks = Qs + 8192;           // [128 d][64 n] swizzled
    float* Vs = Ks + 8192;           // [64 n][128 d] natural
    float* Ps = Vs + 8192;           // [64][65]
    float* sv = Ps + 64 * 65;        // [64] additive mask (0 or -1e30)

    const int qt = blockIdx.x;
    const int h  = blockIdx.y;
    const int b  = blockIdx.z;
    const int kvh = h >> 2;          // GQA: group size 4
    const int t  = threadIdx.x;
    const int ty = t >> 4;
    const int tx = t & 15;

    const size_t tokbase = (size_t)b * SS;
    const float* Qg = qkv + (tokbase + qt * 64) * QKVC + h * HD;
    const unsigned char* visb = vis + tokbase;

    // Load Q tile (transposed + swizzled)
    for (int idx = t; idx < 64 * 32; idx += 256) {
        int row = idx >> 5, d4 = idx & 31;
        float4 v = *(const float4*)(Qg + (size_t)row * QKVC + d4 * 4);
        int c4 = (row >> 2) ^ (d4 & 15);
        int pb = (d4 << 8) + (c4 << 2) + (row & 3);   // (4*d4)*64 + c4*4 + row%4
        Qs[pb] = v.x; Qs[pb + 64] = v.y; Qs[pb + 128] = v.z; Qs[pb + 192] = v.w;
    }

    float m_i[4], l_i[4], o[4][8];
#pragma unroll
    for (int i = 0; i < 4; i++) {
        m_i[i] = -INFINITY; l_i[i] = 0.f;
#pragma unroll
        for (int j = 0; j < 8; j++) o[i][j] = 0.f;
    }
    const float scale = 0.08838834764831843f;  // 1/sqrt(128)

    for (int kt = 0; kt < SS / 64; kt++) {
        __syncthreads();
        const float* Kg = qkv + (tokbase + kt * 64) * QKVC + DIMC + kvh * HD;
        const float* Vg = Kg + NKV * HD;
        for (int idx = t; idx < 64 * 32; idx += 256) {
            int row = idx >> 5, d4 = idx & 31;
            float4 kv4 = *(const float4*)(Kg + (size_t)row * QKVC + d4 * 4);
            int c4 = (row >> 2) ^ (d4 & 15);
            int pb = (d4 << 8) + (c4 << 2) + (row & 3);
            Ks[pb] = kv4.x; Ks[pb + 64] = kv4.y; Ks[pb + 128] = kv4.z; Ks[pb + 192] = kv4.w;
            float4 vv4 = *(const float4*)(Vg + (size_t)row * QKVC + d4 * 4);
            *(float4*)(Vs + (row << 7) + (d4 << 2)) = vv4;
        }
        if (t < 64) sv[t] = visb[kt * 64 + t] ? 0.f : NEGF;
        __syncthreads();

        // S = scale * Q K^T (+ key mask)
        float s4[4][4];
#pragma unroll
        for (int i = 0; i < 4; i++)
#pragma unroll
            for (int j = 0; j < 4; j++) s4[i][j] = 0.f;

#pragma unroll 4
        for (int d = 0; d < 128; d++) {
            int sw = (d >> 2) & 15;
            float4 aq = *(const float4*)&Qs[(d << 6) + ((ty ^ sw) << 2)];
            float4 bk = *(const float4*)&Ks[(d << 6) + ((tx ^ sw) << 2)];
            float a[4] = {aq.x, aq.y, aq.z, aq.w};
            float bb2[4] = {bk.x, bk.y, bk.z, bk.w};
#pragma unroll
            for (int i = 0; i < 4; i++)
#pragma unroll
                for (int j = 0; j < 4; j++) s4[i][j] += a[i] * bb2[j];
        }

        float addm[4];
#pragma unroll
        for (int j = 0; j < 4; j++) addm[j] = sv[tx * 4 + j];

        float alpha[4];
#pragma unroll
        for (int i = 0; i < 4; i++) {
            float rmax = -INFINITY;
#pragma unroll
            for (int j = 0; j < 4; j++) {
                s4[i][j] = s4[i][j] * scale + addm[j];
                rmax = fmaxf(rmax, s4[i][j]);
            }
#pragma unroll
            for (int off = 8; off > 0; off >>= 1)
                rmax = fmaxf(rmax, __shfl_xor_sync(0xffffffffu, rmax, off));
            float mn = fmaxf(m_i[i], rmax);
            float ps = 0.f;
#pragma unroll
            for (int j = 0; j < 4; j++) {
                float p = __expf(s4[i][j] - mn);
                s4[i][j] = p;
                ps += p;
            }
#pragma unroll
            for (int off = 8; off > 0; off >>= 1)
                ps += __shfl_xor_sync(0xffffffffu, ps, off);
            float al = __expf(m_i[i] - mn);
            l_i[i] = l_i[i] * al + ps;
            m_i[i] = mn;
            alpha[i] = al;
#pragma unroll
            for (int j = 0; j < 4; j++)
                Ps[(ty * 4 + i) * 65 + tx * 4 + j] = s4[i][j];
        }
        __syncthreads();

        // O = alpha*O + P V
#pragma unroll
        for (int i = 0; i < 4; i++)
#pragma unroll
            for (int j = 0; j < 8; j++) o[i][j] *= alpha[i];

#pragma unroll 2
        for (int kk = 0; kk < 64; kk++) {
            float4 v0 = *(const float4*)&Vs[(kk << 7) + (tx << 2)];
            float4 v1 = *(const float4*)&Vs[(kk << 7) + 64 + (tx << 2)];
#pragma unroll
            for (int i = 0; i < 4; i++) {
                float p = Ps[(ty * 4 + i) * 65 + kk];
                o[i][0] += p * v0.x; o[i][1] += p * v0.y;
                o[i][2] += p * v0.z; o[i][3] += p * v0.w;
                o[i][4] += p * v1.x; o[i][5] += p * v1.y;
                o[i][6] += p * v1.z; o[i][7] += p * v1.w;
            }
        }
    }

    // Epilogue: normalize; zero fully-invisible query rows (flex semantics)
#pragma unroll
    for (int i = 0; i < 4; i++) {
        int row = qt * 64 + ty * 4 + i;
        float f = visb[row] ? (1.f / l_i[i]) : 0.f;
        float* op = outp + (tokbase + row) * DIMC + h * HD;
        float4 w0 = make_float4(o[i][0] * f, o[i][1] * f, o[i][2] * f, o[i][3] * f);
        float4 w1 = make_float4(o[i][4] * f, o[i][5] * f, o[i][6] * f, o[i][7] * f);
        *(float4*)(op + tx * 4) = w0;
        *(float4*)(op + 64 + tx * 4) = w1;
    }
}

// ---------------------------------------------------------------------------
extern "C" void kernel_launch(void* const* d_in, const int* in_sizes, int n_in,
                              void* d_out, int out_size)
{
    const float* x    = (const float*)d_in[0];
    const float* wqkv = (const float*)d_in[1];
    const float* wo   = (const float*)d_in[2];
    const float* qw   = (const float*)d_in[3];
    const float* kw   = (const float*)d_in[4];
    const float* fc   = (const float*)d_in[5];
    const float* fs   = (const float*)d_in[6];
    const unsigned char* visraw = (const unsigned char*)d_in[7];
    float* out = (float*)d_out;

    float *qkv, *attn;
    unsigned char* mask;
    cudaGetSymbolAddress((void**)&qkv, g_qkv);
    cudaGetSymbolAddress((void**)&attn, g_attn);
    cudaGetSymbolAddress((void**)&mask, g_mask);

    // 0) Canonicalize visibility mask (dtype-robust)
    mask_prep<<<1, 256>>>(visraw);

    // 1) QKV projection: [8192,2048] x [3072,2048]^T
    gemm_nt<<<dim3(QKVC / 128, (BB * SS) / 128), 256>>>(x, wqkv, qkv, BB * SS, QKVC, DIMC);

    // 2) RMSNorm + RoPE on q & k heads (in place)
    norm_rope_kernel<<<dim3(NH + NKV, SS, BB), 128>>>(qkv, qw, kw, fc, fs);

    // 3) Attention
    cudaFuncSetAttribute(attn_kernel, cudaFuncAttributeMaxDynamicSharedMemorySize,
                         ATT_SMEM_BYTES);
    attn_kernel<<<dim3(SS / 64, NH, BB), 256, ATT_SMEM_BYTES>>>(qkv, mask, attn);

    // 4) Output projection: [8192,2048] x [2048,2048]^T
    gemm_nt<<<dim3(DIMC / 128, (BB * SS) / 128), 256>>>(attn, wo, out, BB * SS, DIMC, DIMC);
}